// round 1
// baseline (speedup 1.0000x reference)
#include <cuda_runtime.h>

#define NN 100000
#define EE 600000
#define DD 128
#define D2 256
#define LL 5
#define GG 512
#define BN_EPS 1e-5f

// Scratch (device globals: allocation-free rule)
__device__ __align__(16) float g_h[NN * DD];
__device__ __align__(16) float g_hin[NN * DD];
__device__ __align__(16) float g_agg[NN * DD];
__device__ __align__(16) float g_zmid[(size_t)NN * D2];
__device__ __align__(16) float g_vn[GG * DD];
__device__ __align__(16) float g_vtmp[GG * DD];

// ---------------------------------------------------------------------------
// h = enc_emb[x];  vn = vn_emb broadcast
__global__ void k_init(const int* __restrict__ x, const float* __restrict__ enc,
                       const float* __restrict__ vne) {
    int i = blockIdx.x * blockDim.x + threadIdx.x;
    if (i < NN * DD) {
        int node = i >> 7;
        int d = i & 127;
        g_h[i] = enc[x[node] * DD + d];
    }
    if (i < GG * DD) g_vn[i] = vne[i & 127];
}

// h_in = h + vn[batch]; agg = 0; vtmp = vn  (all vectorized float4)
__global__ void k_hin(const int* __restrict__ batch) {
    int i = blockIdx.x * blockDim.x + threadIdx.x;  // over NN*DD/4
    if (i < NN * DD / 4) {
        int node = i >> 5;          // D/4 = 32 float4 per row
        int off = i & 31;
        float4 h4 = ((const float4*)g_h)[i];
        float4 v4 = ((const float4*)g_vn)[batch[node] * 32 + off];
        float4 r;
        r.x = h4.x + v4.x; r.y = h4.y + v4.y;
        r.z = h4.z + v4.z; r.w = h4.w + v4.w;
        ((float4*)g_hin)[i] = r;
        ((float4*)g_agg)[i] = make_float4(0.f, 0.f, 0.f, 0.f);
    }
    if (i < GG * DD / 4)
        ((float4*)g_vtmp)[i] = ((const float4*)g_vn)[i];
}

// agg[dst] += h_in[src] : one warp per edge, 4 floats per lane
__global__ void k_scatter(const int* __restrict__ ei) {
    int t = blockIdx.x * blockDim.x + threadIdx.x;
    if (t >= EE * 32) return;
    int e = t >> 5;
    int lane = t & 31;
    int s = ei[e];
    int d = ei[EE + e];
    const float* hs = g_hin + (size_t)s * DD;
    float* ag = g_agg + (size_t)d * DD;
#pragma unroll
    for (int r = 0; r < 4; r++) {
        int c = lane + r * 32;
        atomicAdd(&ag[c], hs[c]);
    }
}

// vtmp[batch[i]] += h_in[i]
__global__ void k_vseg(const int* __restrict__ batch) {
    int i = blockIdx.x * blockDim.x + threadIdx.x;
    if (i >= NN * DD) return;
    int node = i >> 7;
    int d = i & 127;
    atomicAdd(&g_vtmp[batch[node] * DD + d], g_hin[i]);
}

// ---------------------------------------------------------------------------
// GEMM1: A[N,128] (fused (1+eps)*h_in + agg)  @  W1[128,256]  -> zmid[N,256]
// epilogue: +b1, BN, ReLU
__global__ __launch_bounds__(256) void k_gemm1(
    int l, const float* __restrict__ eps, const float* __restrict__ W1,
    const float* __restrict__ b1, const float* __restrict__ bg,
    const float* __restrict__ bb, const float* __restrict__ bm,
    const float* __restrict__ bv) {
    __shared__ float As[16][65];
    __shared__ float Bs[16][64];
    int bmRow = blockIdx.x * 64;
    int bnCol = blockIdx.y * 64;
    int tid = threadIdx.x;
    int tr = tid >> 4, tc = tid & 15;
    float ep = 1.f + eps[l];
    const float* Wl = W1 + (size_t)l * DD * D2;
    float acc[4][4];
#pragma unroll
    for (int i = 0; i < 4; i++)
#pragma unroll
        for (int j = 0; j < 4; j++) acc[i][j] = 0.f;

    int ar = tid >> 2, akq = (tid & 3) * 4;    // A tile: 64x16
    int bkr = tid >> 4, bcq = (tid & 15) * 4;  // B tile: 16x64

    for (int k0 = 0; k0 < DD; k0 += 16) {
        int arow = bmRow + ar;
        float4 a4 = make_float4(0.f, 0.f, 0.f, 0.f);
        if (arow < NN) {
            float4 h4 = *(const float4*)(g_hin + (size_t)arow * DD + k0 + akq);
            float4 g4 = *(const float4*)(g_agg + (size_t)arow * DD + k0 + akq);
            a4.x = ep * h4.x + g4.x;
            a4.y = ep * h4.y + g4.y;
            a4.z = ep * h4.z + g4.z;
            a4.w = ep * h4.w + g4.w;
        }
        As[akq + 0][ar] = a4.x;
        As[akq + 1][ar] = a4.y;
        As[akq + 2][ar] = a4.z;
        As[akq + 3][ar] = a4.w;
        *(float4*)&Bs[bkr][bcq] =
            *(const float4*)(Wl + (size_t)(k0 + bkr) * D2 + bnCol + bcq);
        __syncthreads();
#pragma unroll
        for (int k = 0; k < 16; k++) {
            float av[4], bvv[4];
#pragma unroll
            for (int i = 0; i < 4; i++) av[i] = As[k][tr * 4 + i];
#pragma unroll
            for (int j = 0; j < 4; j++) bvv[j] = Bs[k][tc * 4 + j];
#pragma unroll
            for (int i = 0; i < 4; i++)
#pragma unroll
                for (int j = 0; j < 4; j++) acc[i][j] += av[i] * bvv[j];
        }
        __syncthreads();
    }
#pragma unroll
    for (int i = 0; i < 4; i++) {
        int row = bmRow + tr * 4 + i;
        if (row >= NN) continue;
#pragma unroll
        for (int j = 0; j < 4; j++) {
            int col = bnCol + tc * 4 + j;
            float c = acc[i][j] + b1[l * D2 + col];
            c = (c - bm[l * D2 + col]) * rsqrtf(bv[l * D2 + col] + BN_EPS) *
                    bg[l * D2 + col] + bb[l * D2 + col];
            g_zmid[(size_t)row * D2 + col] = fmaxf(c, 0.f);
        }
    }
}

// GEMM2: zmid[N,256] @ W2[256,128] -> h/out[N,128]
// epilogue: +b2, BN, (ReLU unless last layer)
__global__ __launch_bounds__(256) void k_gemm2(
    int l, const float* __restrict__ W2, const float* __restrict__ b2,
    const float* __restrict__ bg, const float* __restrict__ bb,
    const float* __restrict__ bm, const float* __restrict__ bv,
    float* __restrict__ out, int use_out, int do_relu) {
    __shared__ float As[16][65];
    __shared__ float Bs[16][64];
    int bmRow = blockIdx.x * 64;
    int bnCol = blockIdx.y * 64;
    int tid = threadIdx.x;
    int tr = tid >> 4, tc = tid & 15;
    const float* Wl = W2 + (size_t)l * D2 * DD;
    float acc[4][4];
#pragma unroll
    for (int i = 0; i < 4; i++)
#pragma unroll
        for (int j = 0; j < 4; j++) acc[i][j] = 0.f;

    int ar = tid >> 2, akq = (tid & 3) * 4;
    int bkr = tid >> 4, bcq = (tid & 15) * 4;

    for (int k0 = 0; k0 < D2; k0 += 16) {
        int arow = bmRow + ar;
        float4 a4 = make_float4(0.f, 0.f, 0.f, 0.f);
        if (arow < NN)
            a4 = *(const float4*)(g_zmid + (size_t)arow * D2 + k0 + akq);
        As[akq + 0][ar] = a4.x;
        As[akq + 1][ar] = a4.y;
        As[akq + 2][ar] = a4.z;
        As[akq + 3][ar] = a4.w;
        *(float4*)&Bs[bkr][bcq] =
            *(const float4*)(Wl + (size_t)(k0 + bkr) * DD + bnCol + bcq);
        __syncthreads();
#pragma unroll
        for (int k = 0; k < 16; k++) {
            float av[4], bvv[4];
#pragma unroll
            for (int i = 0; i < 4; i++) av[i] = As[k][tr * 4 + i];
#pragma unroll
            for (int j = 0; j < 4; j++) bvv[j] = Bs[k][tc * 4 + j];
#pragma unroll
            for (int i = 0; i < 4; i++)
#pragma unroll
                for (int j = 0; j < 4; j++) acc[i][j] += av[i] * bvv[j];
        }
        __syncthreads();
    }
    float* dst = use_out ? out : g_h;
#pragma unroll
    for (int i = 0; i < 4; i++) {
        int row = bmRow + tr * 4 + i;
        if (row >= NN) continue;
#pragma unroll
        for (int j = 0; j < 4; j++) {
            int col = bnCol + tc * 4 + j;
            float c = acc[i][j] + b2[l * DD + col];
            c = (c - bm[l * DD + col]) * rsqrtf(bv[l * DD + col] + BN_EPS) *
                    bg[l * DD + col] + bb[l * DD + col];
            if (do_relu) c = fmaxf(c, 0.f);
            dst[(size_t)row * DD + col] = c;
        }
    }
}

// ---------------------------------------------------------------------------
// Virtual-node MLP: one block per graph, 256 threads.
__global__ __launch_bounds__(256) void k_vmlp(
    int l, const float* __restrict__ vW1, const float* __restrict__ vb1,
    const float* __restrict__ g1, const float* __restrict__ b1,
    const float* __restrict__ m1, const float* __restrict__ v1,
    const float* __restrict__ vW2, const float* __restrict__ vb2,
    const float* __restrict__ g2, const float* __restrict__ b2,
    const float* __restrict__ m2, const float* __restrict__ v2) {
    __shared__ float row[DD];
    __shared__ float u[D2];
    int g = blockIdx.x;
    int t = threadIdx.x;
    if (t < DD) row[t] = g_vtmp[g * DD + t];
    __syncthreads();
    const float* W1l = vW1 + (size_t)l * DD * D2;
    float s = vb1[l * D2 + t];
#pragma unroll 8
    for (int k = 0; k < DD; k++) s += row[k] * W1l[(size_t)k * D2 + t];
    s = (s - m1[l * D2 + t]) * rsqrtf(v1[l * D2 + t] + BN_EPS) * g1[l * D2 + t] +
        b1[l * D2 + t];
    u[t] = fmaxf(s, 0.f);
    __syncthreads();
    if (t < DD) {
        const float* W2l = vW2 + (size_t)l * D2 * DD;
        float s2 = vb2[l * DD + t];
#pragma unroll 8
        for (int k = 0; k < D2; k++) s2 += u[k] * W2l[(size_t)k * DD + t];
        s2 = (s2 - m2[l * DD + t]) * rsqrtf(v2[l * DD + t] + BN_EPS) *
                 g2[l * DD + t] + b2[l * DD + t];
        g_vn[g * DD + t] = fmaxf(s2, 0.f);
    }
}

// ---------------------------------------------------------------------------
extern "C" void kernel_launch(void* const* d_in, const int* in_sizes, int n_in,
                              void* d_out, int out_size) {
    const int* x = (const int*)d_in[0];
    const int* ei = (const int*)d_in[1];
    const int* batch = (const int*)d_in[2];
    const float* enc = (const float*)d_in[3];
    const float* vne = (const float*)d_in[4];
    const float* eps = (const float*)d_in[5];
    const float* mW1 = (const float*)d_in[6];
    const float* mb1 = (const float*)d_in[7];
    const float* mbn_g = (const float*)d_in[8];
    const float* mbn_b = (const float*)d_in[9];
    const float* mbn_m = (const float*)d_in[10];
    const float* mbn_v = (const float*)d_in[11];
    const float* mW2 = (const float*)d_in[12];
    const float* mb2 = (const float*)d_in[13];
    const float* bn_g = (const float*)d_in[14];
    const float* bn_b = (const float*)d_in[15];
    const float* bn_m = (const float*)d_in[16];
    const float* bn_v = (const float*)d_in[17];
    const float* vW1 = (const float*)d_in[18];
    const float* vb1 = (const float*)d_in[19];
    const float* vbn1_g = (const float*)d_in[20];
    const float* vbn1_b = (const float*)d_in[21];
    const float* vbn1_m = (const float*)d_in[22];
    const float* vbn1_v = (const float*)d_in[23];
    const float* vW2 = (const float*)d_in[24];
    const float* vb2 = (const float*)d_in[25];
    const float* vbn2_g = (const float*)d_in[26];
    const float* vbn2_b = (const float*)d_in[27];
    const float* vbn2_m = (const float*)d_in[28];
    const float* vbn2_v = (const float*)d_in[29];
    float* out = (float*)d_out;

    k_init<<<(NN * DD + 255) / 256, 256>>>(x, enc, vne);
    for (int l = 0; l < LL; l++) {
        k_hin<<<(NN * DD / 4 + 255) / 256, 256>>>(batch);
        k_scatter<<<(EE * 32 + 255) / 256, 256>>>(ei);
        dim3 grid1((NN + 63) / 64, D2 / 64);
        k_gemm1<<<grid1, 256>>>(l, eps, mW1, mb1, mbn_g, mbn_b, mbn_m, mbn_v);
        dim3 grid2((NN + 63) / 64, DD / 64);
        k_gemm2<<<grid2, 256>>>(l, mW2, mb2, bn_g, bn_b, bn_m, bn_v, out,
                                (l == LL - 1) ? 1 : 0, (l < LL - 1) ? 1 : 0);
        if (l < LL - 1) {
            k_vseg<<<(NN * DD + 255) / 256, 256>>>(batch);
            k_vmlp<<<GG, 256>>>(l, vW1, vb1, vbn1_g, vbn1_b, vbn1_m, vbn1_v,
                                vW2, vb2, vbn2_g, vbn2_b, vbn2_m, vbn2_v);
        }
    }
}

// round 2
// speedup vs baseline: 1.2879x; 1.2879x over previous
#include <cuda_runtime.h>

#define NN 100000
#define EE 600000
#define DD 128
#define D2 256
#define LL 5
#define GG 512
#define BN_EPS 1e-5f

// Scratch (device globals: allocation-free rule)
__device__ __align__(16) float g_h[NN * DD];
__device__ __align__(16) float g_hin[NN * DD];
__device__ __align__(16) float g_agg[NN * DD];
__device__ __align__(16) float g_zmid[(size_t)NN * D2];
__device__ __align__(16) float g_vn[GG * DD];
__device__ __align__(16) float g_vtmp[GG * DD];

__device__ __forceinline__ void red_add_v4(float* p, float4 v) {
    asm volatile("red.global.add.v4.f32 [%0], {%1,%2,%3,%4};"
                 :: "l"(p), "f"(v.x), "f"(v.y), "f"(v.z), "f"(v.w)
                 : "memory");
}

// ---------------------------------------------------------------------------
// h = enc_emb[x];  vn = vtmp = vn_emb broadcast
__global__ void k_init(const int* __restrict__ x, const float* __restrict__ enc,
                       const float* __restrict__ vne) {
    int i = blockIdx.x * blockDim.x + threadIdx.x;
    if (i < NN * DD) {
        int node = i >> 7;
        int d = i & 127;
        g_h[i] = enc[x[node] * DD + d];
    }
    if (i < GG * DD) {
        float v = vne[i & 127];
        g_vn[i] = v;
        g_vtmp[i] = v;
    }
}

// h_in = h + vn[batch]; agg = 0; fused: vtmp[batch] += h_in (segment sum)
__global__ void k_hin(const int* __restrict__ batch, int do_vseg) {
    int i = blockIdx.x * blockDim.x + threadIdx.x;  // over NN*DD/4
    if (i >= NN * DD / 4) return;
    int node = i >> 5;  // 32 float4 per row
    int off = i & 31;
    int b = batch[node];
    float4 h4 = ((const float4*)g_h)[i];
    float4 v4 = ((const float4*)g_vn)[b * 32 + off];
    float4 r;
    r.x = h4.x + v4.x; r.y = h4.y + v4.y;
    r.z = h4.z + v4.z; r.w = h4.w + v4.w;
    ((float4*)g_hin)[i] = r;
    ((float4*)g_agg)[i] = make_float4(0.f, 0.f, 0.f, 0.f);
    if (do_vseg) red_add_v4(&g_vtmp[(b * 32 + off) * 4], r);
}

// agg[dst] += h_in[src] : one warp per edge, one v4 red per lane
__global__ void k_scatter(const int* __restrict__ ei) {
    int t = blockIdx.x * blockDim.x + threadIdx.x;
    if (t >= EE * 32) return;
    int e = t >> 5;
    int lane = t & 31;
    int s = ei[e];
    int d = ei[EE + e];
    float4 v = ((const float4*)(g_hin + (size_t)s * DD))[lane];
    red_add_v4(g_agg + (size_t)d * DD + lane * 4, v);
}

// ---------------------------------------------------------------------------
// fp32 GEMM, 128x128 CTA tile, Kc=16, 8x8 microtile, double-buffered smem.
// MODE 0: A = ep*hin + agg [N,128] @ W1 [128,256] -> zmid, epi: b1+BN+ReLU
// MODE 1: A = zmid [N,256] @ W2 [256,128] -> dst,  epi: b2+BN(+ReLU)
template <int KDIM, int NOUT, int MODE>
__global__ __launch_bounds__(256, 2) void k_gemm(
    int l, const float* __restrict__ eps, const float* __restrict__ W,
    const float* __restrict__ bias, const float* __restrict__ bg,
    const float* __restrict__ bb, const float* __restrict__ bm,
    const float* __restrict__ bv, float* __restrict__ out, int use_out,
    int do_relu) {
    __shared__ float As[2][16][132];
    __shared__ float Bs[2][16][128];
    const int tid = threadIdx.x;
    const int row0 = blockIdx.x * 128;
    const int col0 = blockIdx.y * 128;
    const int tx = tid & 15, ty = tid >> 4;
    const float ep = (MODE == 0) ? (1.f + eps[l]) : 0.f;
    const float* Wl = W + (size_t)l * KDIM * NOUT;

    // load mappings
    const int lr = tid >> 1;          // A row in tile (0..127)
    const int lk = (tid & 1) * 8;     // A k base (two float4)
    const int bk = tid >> 4;          // B k row (0..15)
    const int bc = (tid & 15) * 8;    // B col base (two float4)

    float acc[8][8];
#pragma unroll
    for (int i = 0; i < 8; i++)
#pragma unroll
        for (int j = 0; j < 8; j++) acc[i][j] = 0.f;

    const int arow = row0 + lr;
    const bool aok = arow < NN;

    // --- load tile 0 directly ---
    {
        float4 a0 = make_float4(0, 0, 0, 0), a1 = a0;
        if (aok) {
            if (MODE == 0) {
                const float* hp = g_hin + (size_t)arow * KDIM + lk;
                const float* gp = g_agg + (size_t)arow * KDIM + lk;
                float4 h0 = *(const float4*)hp, h1 = *(const float4*)(hp + 4);
                float4 q0 = *(const float4*)gp, q1 = *(const float4*)(gp + 4);
                a0.x = ep * h0.x + q0.x; a0.y = ep * h0.y + q0.y;
                a0.z = ep * h0.z + q0.z; a0.w = ep * h0.w + q0.w;
                a1.x = ep * h1.x + q1.x; a1.y = ep * h1.y + q1.y;
                a1.z = ep * h1.z + q1.z; a1.w = ep * h1.w + q1.w;
            } else {
                const float* zp = g_zmid + (size_t)arow * KDIM + lk;
                a0 = *(const float4*)zp;
                a1 = *(const float4*)(zp + 4);
            }
        }
        As[0][lk + 0][lr] = a0.x; As[0][lk + 1][lr] = a0.y;
        As[0][lk + 2][lr] = a0.z; As[0][lk + 3][lr] = a0.w;
        As[0][lk + 4][lr] = a1.x; As[0][lk + 5][lr] = a1.y;
        As[0][lk + 6][lr] = a1.z; As[0][lk + 7][lr] = a1.w;
        const float* wp = Wl + (size_t)bk * NOUT + col0 + bc;
        *(float4*)&Bs[0][bk][bc] = *(const float4*)wp;
        *(float4*)&Bs[0][bk][bc + 4] = *(const float4*)(wp + 4);
    }
    __syncthreads();

    const int KT = KDIM / 16;
    int buf = 0;
#pragma unroll 1
    for (int kt = 0; kt < KT; kt++) {
        float4 pa0, pa1, pb0, pb1;
        if (kt + 1 < KT) {
            const int kg = (kt + 1) * 16;
            pa0 = make_float4(0, 0, 0, 0); pa1 = pa0;
            if (aok) {
                if (MODE == 0) {
                    const float* hp = g_hin + (size_t)arow * KDIM + kg + lk;
                    const float* gp = g_agg + (size_t)arow * KDIM + kg + lk;
                    float4 h0 = *(const float4*)hp, h1 = *(const float4*)(hp + 4);
                    float4 q0 = *(const float4*)gp, q1 = *(const float4*)(gp + 4);
                    pa0.x = ep * h0.x + q0.x; pa0.y = ep * h0.y + q0.y;
                    pa0.z = ep * h0.z + q0.z; pa0.w = ep * h0.w + q0.w;
                    pa1.x = ep * h1.x + q1.x; pa1.y = ep * h1.y + q1.y;
                    pa1.z = ep * h1.z + q1.z; pa1.w = ep * h1.w + q1.w;
                } else {
                    const float* zp = g_zmid + (size_t)arow * KDIM + kg + lk;
                    pa0 = *(const float4*)zp;
                    pa1 = *(const float4*)(zp + 4);
                }
            }
            const float* wp = Wl + (size_t)(kg + bk) * NOUT + col0 + bc;
            pb0 = *(const float4*)wp;
            pb1 = *(const float4*)(wp + 4);
        }
        // compute on buf
#pragma unroll
        for (int k = 0; k < 16; k++) {
            float av[8], bvv[8];
            *(float4*)&av[0] = *(const float4*)&As[buf][k][ty * 8];
            *(float4*)&av[4] = *(const float4*)&As[buf][k][ty * 8 + 4];
            *(float4*)&bvv[0] = *(const float4*)&Bs[buf][k][tx * 8];
            *(float4*)&bvv[4] = *(const float4*)&Bs[buf][k][tx * 8 + 4];
#pragma unroll
            for (int i = 0; i < 8; i++)
#pragma unroll
                for (int j = 0; j < 8; j++) acc[i][j] += av[i] * bvv[j];
        }
        if (kt + 1 < KT) {
            int nb = buf ^ 1;
            As[nb][lk + 0][lr] = pa0.x; As[nb][lk + 1][lr] = pa0.y;
            As[nb][lk + 2][lr] = pa0.z; As[nb][lk + 3][lr] = pa0.w;
            As[nb][lk + 4][lr] = pa1.x; As[nb][lk + 5][lr] = pa1.y;
            As[nb][lk + 6][lr] = pa1.z; As[nb][lk + 7][lr] = pa1.w;
            *(float4*)&Bs[nb][bk][bc] = pb0;
            *(float4*)&Bs[nb][bk][bc + 4] = pb1;
            __syncthreads();
            buf = nb;
        }
    }

    // epilogue: per-col affine precompute
    float sc[8], off[8];
#pragma unroll
    for (int j = 0; j < 8; j++) {
        int col = col0 + tx * 8 + j;
        float s = rsqrtf(bv[l * NOUT + col] + BN_EPS) * bg[l * NOUT + col];
        sc[j] = s;
        off[j] = (bias[l * NOUT + col] - bm[l * NOUT + col]) * s +
                 bb[l * NOUT + col];
    }
    float* dst;
    if (MODE == 0) dst = g_zmid;
    else dst = use_out ? out : g_h;
#pragma unroll
    for (int i = 0; i < 8; i++) {
        int row = row0 + ty * 8 + i;
        if (row >= NN) continue;
        float* dp = dst + (size_t)row * NOUT + col0 + tx * 8;
        float4 o0, o1;
        float v[8];
#pragma unroll
        for (int j = 0; j < 8; j++) {
            float c = acc[i][j] * sc[j] + off[j];
            if (MODE == 0) c = fmaxf(c, 0.f);
            else if (do_relu) c = fmaxf(c, 0.f);
            v[j] = c;
        }
        o0 = make_float4(v[0], v[1], v[2], v[3]);
        o1 = make_float4(v[4], v[5], v[6], v[7]);
        *(float4*)dp = o0;
        *(float4*)(dp + 4) = o1;
    }
}

// ---------------------------------------------------------------------------
// Virtual-node MLP: one block per graph, 256 threads. Also seeds vtmp=vn.
__global__ __launch_bounds__(256) void k_vmlp(
    int l, const float* __restrict__ vW1, const float* __restrict__ vb1,
    const float* __restrict__ g1, const float* __restrict__ b1,
    const float* __restrict__ m1, const float* __restrict__ v1,
    const float* __restrict__ vW2, const float* __restrict__ vb2,
    const float* __restrict__ g2, const float* __restrict__ b2,
    const float* __restrict__ m2, const float* __restrict__ v2) {
    __shared__ float row[DD];
    __shared__ float u[D2];
    int g = blockIdx.x;
    int t = threadIdx.x;
    if (t < DD) row[t] = g_vtmp[g * DD + t];
    __syncthreads();
    const float* W1l = vW1 + (size_t)l * DD * D2;
    float s = vb1[l * D2 + t];
#pragma unroll 8
    for (int k = 0; k < DD; k++) s += row[k] * W1l[(size_t)k * D2 + t];
    s = (s - m1[l * D2 + t]) * rsqrtf(v1[l * D2 + t] + BN_EPS) * g1[l * D2 + t] +
        b1[l * D2 + t];
    u[t] = fmaxf(s, 0.f);
    __syncthreads();
    if (t < DD) {
        const float* W2l = vW2 + (size_t)l * D2 * DD;
        float s2 = vb2[l * DD + t];
#pragma unroll 8
        for (int k = 0; k < D2; k++) s2 += u[k] * W2l[(size_t)k * DD + t];
        s2 = (s2 - m2[l * DD + t]) * rsqrtf(v2[l * DD + t] + BN_EPS) *
                 g2[l * DD + t] + b2[l * DD + t];
        float r = fmaxf(s2, 0.f);
        g_vn[g * DD + t] = r;
        g_vtmp[g * DD + t] = r;  // seed next layer's segment sum
    }
}

// ---------------------------------------------------------------------------
extern "C" void kernel_launch(void* const* d_in, const int* in_sizes, int n_in,
                              void* d_out, int out_size) {
    const int* x = (const int*)d_in[0];
    const int* ei = (const int*)d_in[1];
    const int* batch = (const int*)d_in[2];
    const float* enc = (const float*)d_in[3];
    const float* vne = (const float*)d_in[4];
    const float* eps = (const float*)d_in[5];
    const float* mW1 = (const float*)d_in[6];
    const float* mb1 = (const float*)d_in[7];
    const float* mbn_g = (const float*)d_in[8];
    const float* mbn_b = (const float*)d_in[9];
    const float* mbn_m = (const float*)d_in[10];
    const float* mbn_v = (const float*)d_in[11];
    const float* mW2 = (const float*)d_in[12];
    const float* mb2 = (const float*)d_in[13];
    const float* bn_g = (const float*)d_in[14];
    const float* bn_b = (const float*)d_in[15];
    const float* bn_m = (const float*)d_in[16];
    const float* bn_v = (const float*)d_in[17];
    const float* vW1 = (const float*)d_in[18];
    const float* vb1 = (const float*)d_in[19];
    const float* vbn1_g = (const float*)d_in[20];
    const float* vbn1_b = (const float*)d_in[21];
    const float* vbn1_m = (const float*)d_in[22];
    const float* vbn1_v = (const float*)d_in[23];
    const float* vW2 = (const float*)d_in[24];
    const float* vb2 = (const float*)d_in[25];
    const float* vbn2_g = (const float*)d_in[26];
    const float* vbn2_b = (const float*)d_in[27];
    const float* vbn2_m = (const float*)d_in[28];
    const float* vbn2_v = (const float*)d_in[29];
    float* out = (float*)d_out;

    k_init<<<(NN * DD + 255) / 256, 256>>>(x, enc, vne);
    for (int l = 0; l < LL; l++) {
        k_hin<<<(NN * DD / 4 + 255) / 256, 256>>>(batch, (l < LL - 1) ? 1 : 0);
        k_scatter<<<(EE * 32 + 255) / 256, 256>>>(ei);
        dim3 grid1((NN + 127) / 128, D2 / 128);
        k_gemm<DD, D2, 0><<<grid1, 256>>>(l, eps, mW1, mb1, mbn_g, mbn_b,
                                          mbn_m, mbn_v, out, 0, 0);
        dim3 grid2((NN + 127) / 128, DD / 128);
        k_gemm<D2, DD, 1><<<grid2, 256>>>(l, eps, mW2, mb2, bn_g, bn_b, bn_m,
                                          bn_v, out, (l == LL - 1) ? 1 : 0,
                                          (l < LL - 1) ? 1 : 0);
        if (l < LL - 1) {
            k_vmlp<<<GG, 256>>>(l, vW1, vb1, vbn1_g, vbn1_b, vbn1_m, vbn1_v,
                                vW2, vb2, vbn2_g, vbn2_b, vbn2_m, vbn2_v);
        }
    }
}

// round 5
// speedup vs baseline: 1.6905x; 1.3126x over previous
#include <cuda_runtime.h>
#include <cstdint>

#define NN 100000
#define EE 600000
#define DD 128
#define D2 256
#define LL 5
#define GG 512
#define BN_EPS 1e-5f

#define KC 32  // K chunk per smem stage

// Scratch (device globals: allocation-free rule)
__device__ __align__(16) float g_h[NN * DD];
__device__ __align__(16) float g_hin[NN * DD];
__device__ __align__(16) float g_agg[NN * DD];
__device__ __align__(16) float g_zmid[(size_t)NN * D2];
__device__ __align__(16) float g_vn[GG * DD];
__device__ __align__(16) float g_vtmp[GG * DD];
__device__ __align__(16) float g_w1t[LL * D2 * DD];  // W1^T: [l][n=256][k=128]
__device__ __align__(16) float g_w2t[LL * DD * D2];  // W2^T: [l][n=128][k=256]

// ---------------------------------------------------------------------------
__device__ __forceinline__ uint32_t smem_u32(const void* p) {
    uint32_t a;
    asm("{ .reg .u64 t; cvta.to.shared.u64 t, %1; cvt.u32.u64 %0, t; }"
        : "=r"(a) : "l"(p));
    return a;
}
__device__ __forceinline__ void cp16(uint32_t d, const void* s, int sz) {
    asm volatile("cp.async.ca.shared.global [%0], [%1], 16, %2;"
                 :: "r"(d), "l"(s), "r"(sz) : "memory");
}
__device__ __forceinline__ void cp_commit() {
    asm volatile("cp.async.commit_group;" ::: "memory");
}
__device__ __forceinline__ void cp_wait1() {
    asm volatile("cp.async.wait_group 1;" ::: "memory");
}
__device__ __forceinline__ void cp_wait0() {
    asm volatile("cp.async.wait_group 0;" ::: "memory");
}
__device__ __forceinline__ void ldm4(uint32_t* r, uint32_t addr) {
    asm volatile("ldmatrix.sync.aligned.m8n8.x4.shared.b16 {%0,%1,%2,%3}, [%4];"
                 : "=r"(r[0]), "=r"(r[1]), "=r"(r[2]), "=r"(r[3]) : "r"(addr));
}
__device__ __forceinline__ void mma8(float* c, const uint32_t* a,
                                     const uint32_t* b) {
    asm volatile(
        "mma.sync.aligned.m16n8k8.row.col.f32.tf32.tf32.f32 "
        "{%0,%1,%2,%3}, {%4,%5,%6,%7}, {%8,%9}, {%0,%1,%2,%3};"
        : "+f"(c[0]), "+f"(c[1]), "+f"(c[2]), "+f"(c[3])
        : "r"(a[0]), "r"(a[1]), "r"(a[2]), "r"(a[3]), "r"(b[0]), "r"(b[1]));
}
__device__ __forceinline__ uint32_t cvt_tf32(float f) {
    uint32_t u;
    asm("cvt.rna.tf32.f32 %0, %1;" : "=r"(u) : "f"(f));
    return u;
}
// 3xTF32 split: hi = rn_tf32(x), lo = rn_tf32(x - hi)
__device__ __forceinline__ void split_tf32(uint32_t in, uint32_t& hi,
                                           uint32_t& lo) {
    float f = __uint_as_float(in);
    hi = cvt_tf32(f);
    lo = cvt_tf32(f - __uint_as_float(hi));
}
// rotation swizzle: tile row r (128B), 16B block cb -> conflict-free
__device__ __forceinline__ uint32_t swadr(uint32_t base, int r, int cb) {
    return base + (uint32_t)(r * 128 + (((cb + r) & 7) << 4));
}
__device__ __forceinline__ void red_add_v4(float* p, float4 v) {
    asm volatile("red.global.add.v4.f32 [%0], {%1,%2,%3,%4};"
                 :: "l"(p), "f"(v.x), "f"(v.y), "f"(v.z), "f"(v.w)
                 : "memory");
}

// ---------------------------------------------------------------------------
// weight transpose: Wt[l][n][k] = W[l][k][n]
__global__ void k_wt(const float* __restrict__ W, float* __restrict__ Wt,
                     int K, int N) {
    __shared__ float t[32][33];
    int l = blockIdx.z;
    int k0 = blockIdx.x * 32, n0 = blockIdx.y * 32;
    const float* Wl = W + (size_t)l * K * N;
    float* Wtl = Wt + (size_t)l * K * N;
    int tx = threadIdx.x, ty = threadIdx.y;  // 32 x 8
#pragma unroll
    for (int i = 0; i < 4; i++)
        t[ty + i * 8][tx] = Wl[(size_t)(k0 + ty + i * 8) * N + n0 + tx];
    __syncthreads();
#pragma unroll
    for (int i = 0; i < 4; i++)
        Wtl[(size_t)(n0 + ty + i * 8) * K + k0 + tx] = t[tx][ty + i * 8];
}

// ---------------------------------------------------------------------------
// h = enc_emb[x];  vn = vtmp = vn_emb broadcast
__global__ void k_init(const int* __restrict__ x, const float* __restrict__ enc,
                       const float* __restrict__ vne) {
    int i = blockIdx.x * blockDim.x + threadIdx.x;
    if (i < NN * DD) {
        int node = i >> 7;
        int d = i & 127;
        g_h[i] = enc[x[node] * DD + d];
    }
    if (i < GG * DD) {
        float v = vne[i & 127];
        g_vn[i] = v;
        g_vtmp[i] = v;
    }
}

// h_in = h + vn[batch]; agg = (1+eps)*h_in; optional vtmp[batch] += h_in
__global__ void k_hin(const int* __restrict__ batch, int do_vseg,
                      const float* __restrict__ eps, int l) {
    int i = blockIdx.x * blockDim.x + threadIdx.x;
    if (i >= NN * DD / 4) return;
    float ep = 1.f + eps[l];
    int node = i >> 5;
    int off = i & 31;
    int b = batch[node];
    float4 h4 = ((const float4*)g_h)[i];
    float4 v4 = ((const float4*)g_vn)[b * 32 + off];
    float4 r;
    r.x = h4.x + v4.x; r.y = h4.y + v4.y;
    r.z = h4.z + v4.z; r.w = h4.w + v4.w;
    ((float4*)g_hin)[i] = r;
    float4 a;
    a.x = ep * r.x; a.y = ep * r.y; a.z = ep * r.z; a.w = ep * r.w;
    ((float4*)g_agg)[i] = a;
    if (do_vseg) red_add_v4(&g_vtmp[(b * 32 + off) * 4], r);
}

// agg[dst] += h_in[src] : one warp per edge, one v4 red per lane
__global__ void k_scatter(const int* __restrict__ ei) {
    int t = blockIdx.x * blockDim.x + threadIdx.x;
    if (t >= EE * 32) return;
    int e = t >> 5;
    int lane = t & 31;
    int s = ei[e];
    int d = ei[EE + e];
    float4 v = ((const float4*)(g_hin + (size_t)s * DD))[lane];
    red_add_v4(g_agg + (size_t)d * DD + lane * 4, v);
}

// ---------------------------------------------------------------------------
// 3xTF32 mma.sync GEMM. CTA 128x128, warp 64x32, KC=32 double-buffered.
// MODE 0: A=g_agg [N,128]  @ W1 -> zmid (+b,BN,ReLU)
// MODE 1: A=g_zmid [N,256] @ W2 -> dst  (+b,BN,[ReLU])
#define SM_BYTES (65536 + 1024)

template <int KDIM, int NOUT, int MODE>
__global__ __launch_bounds__(256, 2) void k_gemm_mma(
    int l, const float* __restrict__ bias, const float* __restrict__ bg,
    const float* __restrict__ bb, const float* __restrict__ bm,
    const float* __restrict__ bv, float* __restrict__ out, int use_out,
    int do_relu) {
    extern __shared__ char smraw[];
    uint32_t sraw = smem_u32(smraw);
    uint32_t s0 = (sraw + 1023) & ~1023u;
    const uint32_t sA = s0, sB = s0 + 32768;

    const int tid = threadIdx.x;
    const int wid = tid >> 5, lane = tid & 31;
    const int wm = wid & 1, wn = wid >> 1;  // warp 64x32: row wm*64, col wn*32
    const int row0 = blockIdx.x * 128;
    const int col0 = blockIdx.y * 128;

    const float* Asrc = MODE ? g_zmid : g_agg;
    const float* Wt = (MODE ? g_w2t : g_w1t) + (size_t)l * NOUT * KDIM;

    float c[4][4][4];
#pragma unroll
    for (int i = 0; i < 4; i++)
#pragma unroll
        for (int j = 0; j < 4; j++)
#pragma unroll
            for (int q = 0; q < 4; q++) c[i][j][q] = 0.f;

    auto load_stage = [&](int ch, int buf) {
#pragma unroll
        for (int i = 0; i < 4; i++) {
            int j = tid + i * 256;
            int r = j >> 3, cb = j & 7;
            int grow = row0 + r;
            cp16(swadr(sA + buf * 16384, r, cb),
                 Asrc + (size_t)grow * KDIM + ch * KC + cb * 4,
                 (grow < NN) ? 16 : 0);
        }
#pragma unroll
        for (int i = 0; i < 4; i++) {
            int j = tid + i * 256;
            int n = j >> 3, cb = j & 7;
            cp16(swadr(sB + buf * 16384, n, cb),
                 Wt + (size_t)(col0 + n) * KDIM + ch * KC + cb * 4, 16);
        }
    };

    // fragment address params
    const int rAb = wm * 64 + (lane & 15);
    const int cAb = lane >> 4;  // 0/1
    const int rBb = wn * 32 + (lane & 7) + ((lane & 16) >> 1);
    const int cBb = (lane >> 3) & 1;

    const int NCH = KDIM / KC;
    load_stage(0, 0);
    cp_commit();
    int buf = 0;
#pragma unroll 1
    for (int ch = 0; ch < NCH; ch++) {
        if (ch + 1 < NCH) {
            load_stage(ch + 1, buf ^ 1);
            cp_commit();
            cp_wait1();
        } else {
            cp_wait0();
        }
        __syncthreads();
        uint32_t a_base = sA + buf * 16384;
        uint32_t b_base = sB + buf * 16384;
#pragma unroll
        for (int kk = 0; kk < 4; kk++) {
            uint32_t bfr[2][4], bh[2][4], bl[2][4];
#pragma unroll
            for (int np = 0; np < 2; np++) {
                ldm4(bfr[np], swadr(b_base, rBb + np * 16, cBb + kk * 2));
#pragma unroll
                for (int q = 0; q < 4; q++)
                    split_tf32(bfr[np][q], bh[np][q], bl[np][q]);
            }
#pragma unroll
            for (int ma = 0; ma < 4; ma++) {
                uint32_t afr[4], ah[4], al[4];
                ldm4(afr, swadr(a_base, rAb + ma * 16, cAb + kk * 2));
#pragma unroll
                for (int q = 0; q < 4; q++) split_tf32(afr[q], ah[q], al[q]);
#pragma unroll
                for (int na = 0; na < 4; na++) {
                    const uint32_t* bhp = &bh[na >> 1][(na & 1) * 2];
                    const uint32_t* blp = &bl[na >> 1][(na & 1) * 2];
                    mma8(c[ma][na], ah, bhp);
                    mma8(c[ma][na], al, bhp);
                    mma8(c[ma][na], ah, blp);
                }
            }
        }
        __syncthreads();
        buf ^= 1;
    }

    // epilogue: per-thread BN params for its 8 columns
    float sc2[4][2], of2[4][2];
#pragma unroll
    for (int na = 0; na < 4; na++) {
#pragma unroll
        for (int q = 0; q < 2; q++) {
            int col = col0 + wn * 32 + na * 8 + (lane & 3) * 2 + q;
            float s = rsqrtf(bv[l * NOUT + col] + BN_EPS) * bg[l * NOUT + col];
            sc2[na][q] = s;
            of2[na][q] = (bias[l * NOUT + col] - bm[l * NOUT + col]) * s +
                         bb[l * NOUT + col];
        }
    }
    float* dst = MODE ? (use_out ? out : g_h) : g_zmid;
    const bool relu = (MODE == 0) || do_relu;
#pragma unroll
    for (int ma = 0; ma < 4; ma++) {
#pragma unroll
        for (int rr = 0; rr < 2; rr++) {
            int grow = row0 + wm * 64 + ma * 16 + (lane >> 2) + rr * 8;
            if (grow >= NN) continue;
            float* dp = dst + (size_t)grow * NOUT + col0 + wn * 32 +
                        (lane & 3) * 2;
#pragma unroll
            for (int na = 0; na < 4; na++) {
                float v0 = c[ma][na][rr * 2 + 0] * sc2[na][0] + of2[na][0];
                float v1 = c[ma][na][rr * 2 + 1] * sc2[na][1] + of2[na][1];
                if (relu) { v0 = fmaxf(v0, 0.f); v1 = fmaxf(v1, 0.f); }
                *(float2*)(dp + na * 8) = make_float2(v0, v1);
            }
        }
    }
}

// ---------------------------------------------------------------------------
// Virtual-node MLP: one block per graph. Also re-seeds vtmp=vn.
__global__ __launch_bounds__(256) void k_vmlp(
    int l, const float* __restrict__ vW1, const float* __restrict__ vb1,
    const float* __restrict__ g1, const float* __restrict__ b1,
    const float* __restrict__ m1, const float* __restrict__ v1,
    const float* __restrict__ vW2, const float* __restrict__ vb2,
    const float* __restrict__ g2, const float* __restrict__ b2,
    const float* __restrict__ m2, const float* __restrict__ v2) {
    __shared__ float row[DD];
    __shared__ float u[D2];
    int g = blockIdx.x;
    int t = threadIdx.x;
    if (t < DD) row[t] = g_vtmp[g * DD + t];
    __syncthreads();
    const float* W1l = vW1 + (size_t)l * DD * D2;
    float s = vb1[l * D2 + t];
#pragma unroll 8
    for (int k = 0; k < DD; k++) s += row[k] * W1l[(size_t)k * D2 + t];
    s = (s - m1[l * D2 + t]) * rsqrtf(v1[l * D2 + t] + BN_EPS) * g1[l * D2 + t] +
        b1[l * D2 + t];
    u[t] = fmaxf(s, 0.f);
    __syncthreads();
    if (t < DD) {
        const float* W2l = vW2 + (size_t)l * D2 * DD;
        float s2 = vb2[l * DD + t];
#pragma unroll 8
        for (int k = 0; k < D2; k++) s2 += u[k] * W2l[(size_t)k * DD + t];
        s2 = (s2 - m2[l * DD + t]) * rsqrtf(v2[l * DD + t] + BN_EPS) *
                 g2[l * DD + t] + b2[l * DD + t];
        float r = fmaxf(s2, 0.f);
        g_vn[g * DD + t] = r;
        g_vtmp[g * DD + t] = r;
    }
}

// ---------------------------------------------------------------------------
extern "C" void kernel_launch(void* const* d_in, const int* in_sizes, int n_in,
                              void* d_out, int out_size) {
    const int* x = (const int*)d_in[0];
    const int* ei = (const int*)d_in[1];
    const int* batch = (const int*)d_in[2];
    const float* enc = (const float*)d_in[3];
    const float* vne = (const float*)d_in[4];
    const float* eps = (const float*)d_in[5];
    const float* mW1 = (const float*)d_in[6];
    const float* mb1 = (const float*)d_in[7];
    const float* mbn_g = (const float*)d_in[8];
    const float* mbn_b = (const float*)d_in[9];
    const float* mbn_m = (const float*)d_in[10];
    const float* mbn_v = (const float*)d_in[11];
    const float* mW2 = (const float*)d_in[12];
    const float* mb2 = (const float*)d_in[13];
    const float* bn_g = (const float*)d_in[14];
    const float* bn_b = (const float*)d_in[15];
    const float* bn_m = (const float*)d_in[16];
    const float* bn_v = (const float*)d_in[17];
    const float* vW1 = (const float*)d_in[18];
    const float* vb1 = (const float*)d_in[19];
    const float* vbn1_g = (const float*)d_in[20];
    const float* vbn1_b = (const float*)d_in[21];
    const float* vbn1_m = (const float*)d_in[22];
    const float* vbn1_v = (const float*)d_in[23];
    const float* vW2 = (const float*)d_in[24];
    const float* vb2 = (const float*)d_in[25];
    const float* vbn2_g = (const float*)d_in[26];
    const float* vbn2_b = (const float*)d_in[27];
    const float* vbn2_m = (const float*)d_in[28];
    const float* vbn2_v = (const float*)d_in[29];
    float* out = (float*)d_out;

    cudaFuncSetAttribute(k_gemm_mma<DD, D2, 0>,
                         cudaFuncAttributeMaxDynamicSharedMemorySize, SM_BYTES);
    cudaFuncSetAttribute(k_gemm_mma<D2, DD, 1>,
                         cudaFuncAttributeMaxDynamicSharedMemorySize, SM_BYTES);

    // per-launch: transpose weights into [n][k] scratch
    {
        float* w1t; cudaGetSymbolAddress((void**)&w1t, g_w1t);
        float* w2t; cudaGetSymbolAddress((void**)&w2t, g_w2t);
        dim3 tb(32, 8);
        dim3 g1(DD / 32, D2 / 32, LL);
        k_wt<<<g1, tb>>>(mW1, w1t, DD, D2);
        dim3 g2(D2 / 32, DD / 32, LL);
        k_wt<<<g2, tb>>>(mW2, w2t, D2, DD);
    }

    k_init<<<(NN * DD + 255) / 256, 256>>>(x, enc, vne);
    for (int l = 0; l < LL; l++) {
        k_hin<<<(NN * DD / 4 + 255) / 256, 256>>>(batch, (l < LL - 1) ? 1 : 0,
                                                  eps, l);
        k_scatter<<<(EE * 32 + 255) / 256, 256>>>(ei);
        dim3 grid1((NN + 127) / 128, D2 / 128);
        k_gemm_mma<DD, D2, 0><<<grid1, 256, SM_BYTES>>>(
            l, mb1, mbn_g, mbn_b, mbn_m, mbn_v, out, 0, 0);
        dim3 grid2((NN + 127) / 128, DD / 128);
        k_gemm_mma<D2, DD, 1><<<grid2, 256, SM_BYTES>>>(
            l, mb2, bn_g, bn_b, bn_m, bn_v, out, (l == LL - 1) ? 1 : 0,
            (l < LL - 1) ? 1 : 0);
        if (l < LL - 1) {
            k_vmlp<<<GG, 256>>>(l, vW1, vb1, vbn1_g, vbn1_b, vbn1_m, vbn1_v,
                                vW2, vb2, vbn2_g, vbn2_b, vbn2_m, vbn2_v);
        }
    }
}